// round 2
// baseline (speedup 1.0000x reference)
#include <cuda_runtime.h>
#include <math.h>

#define BB  4
#define NXX 512
#define NYY 512
#define DVV 32
#define KXX 64
#define KYY 64

#define PI_D 3.14159265358979323846

typedef unsigned long long u64;

// packed fp32x2 FMA: d.lo += a.lo*b.lo; d.hi += a.hi*b.hi  (SASS FFMA2, 2x fp32 rate)
__device__ __forceinline__ void ffma2(u64 &d, u64 a, u64 b) {
    asm("fma.rn.f32x2 %0, %1, %2, %0;" : "+l"(d) : "l"(a), "l"(b));
}
__device__ __forceinline__ float2 unpack2(u64 v) {
    float2 r;
    asm("mov.b64 {%0,%1}, %2;" : "=f"(r.x), "=f"(r.y) : "l"(v));
    return r;
}

// Transform matrices (both orientations so smem staging is always a linear copy)
__device__ __align__(16) float g_Ct [NYY*KYY];   // Ct[n][k]  DCT-II fwd, k-minor
__device__ __align__(16) float g_Cr [KYY*NYY];   // C [k][n]  DCT (used for iDCT = C^T)
__device__ __align__(16) float g_Ftr[NXX*KXX];   // fwd rfft real, [n][k]
__device__ __align__(16) float g_Fti[NXX*KXX];   // fwd rfft imag, [n][k]
__device__ __align__(16) float g_Gr [KXX*NXX];   // inv rfft wt for Yr, [k][n]
__device__ __align__(16) float g_Gi [KXX*NXX];   // inv rfft wt for Yi, [k][n]

// Scratch
__device__ __align__(16) float g_S1 [(size_t)BB*NXX*KYY*DVV];  // [b][nx][ky][dv]
__device__ __align__(16) float g_S2r[(size_t)BB*KXX*KYY*DVV];  // [b][kx][ky][dv]
__device__ __align__(16) float g_S2i[(size_t)BB*KXX*KYY*DVV];
__device__ __align__(16) float g_S3r[(size_t)BB*KYY*KXX*DVV];  // [b][ky][kx][dv]
__device__ __align__(16) float g_S3i[(size_t)BB*KYY*KXX*DVV];
__device__ __align__(16) float g_S4 [(size_t)BB*NXX*KYY*DVV];  // [b][nx][ky][dv]

// ---------------------------------------------------------------------------
// Precompute transform matrices (fp64 trig, exact mod reduction of angles).
// ---------------------------------------------------------------------------
__global__ void k_precompute() {
    int idx = blockIdx.x * blockDim.x + threadIdx.x;
    if (idx >= KXX * NXX) return;
    int k = idx >> 9;
    int n = idx & 511;

    double sk = (k == 0) ? sqrt(1.0 / 512.0) : sqrt(2.0 / 512.0);
    int m = (k * (2 * n + 1)) & 2047;
    float Ckn = (float)(sk * cos(PI_D * (double)m / 1024.0));
    g_Cr[k * 512 + n] = Ckn;
    g_Ct[n * 64 + k]  = Ckn;

    int mm = (k * n) & 511;
    double ang = 2.0 * PI_D * (double)mm / 512.0;
    double isq = sqrt(1.0 / 512.0);
    float fr = (float)( cos(ang) * isq);
    float fi = (float)(-sin(ang) * isq);
    g_Ftr[n * 64 + k] = fr;
    g_Fti[n * 64 + k] = fi;
    float ck = (k == 0) ? 1.0f : 2.0f;
    g_Gr[k * 512 + n] = ck * fr;
    g_Gi[k * 512 + n] = ck * fi;
}

// ---------------------------------------------------------------------------
// Step 1: DCT-Y forward, truncated. S1[b][nx][ky][dv] = sum_ny Ct[ny][ky]*x[..][ny][dv]
// grid (NX, B), 128 threads. Packed pairs along ky; B duplicated in smem.
// ---------------------------------------------------------------------------
__global__ __launch_bounds__(128) void k_step1(const float* __restrict__ x) {
    __shared__ float As[64 * 64];   // [nn][ky]
    __shared__ float Bs[64 * 64];   // [nn][dv duplicated pairs]
    int nx = blockIdx.x, b = blockIdx.y;
    int tid = threadIdx.x;
    int dg = tid & 7;               // dv0 = 4*dg
    int kg = tid >> 3;              // ky0 = 4*kg
    const float* xin = x + ((size_t)(b * NXX + nx)) * NYY * DVV;

    u64 acc[2][4] = {};             // [ky-pair][dv]
    for (int c = 0; c < 8; ++c) {
        const float4* sa = (const float4*)(g_Ct + c * 64 * 64);
        float4* da = (float4*)As;
#pragma unroll
        for (int t = 0; t < 8; ++t) da[tid + 128 * t] = sa[tid + 128 * t];
        const float4* sb = (const float4*)(xin + c * 64 * 32);
#pragma unroll
        for (int t = 0; t < 4; ++t) {
            int j = tid + 128 * t;
            float4 v = sb[j];
            int nn = j >> 3, q = j & 7;
            float4* drow = (float4*)(Bs + nn * 64 + 8 * q);
            drow[0] = make_float4(v.x, v.x, v.y, v.y);
            drow[1] = make_float4(v.z, v.z, v.w, v.w);
        }
        __syncthreads();
#pragma unroll 8
        for (int nn = 0; nn < 64; ++nn) {
            ulonglong2 ap = *(const ulonglong2*)(As + nn * 64 + 4 * kg);
            ulonglong2 b0 = *(const ulonglong2*)(Bs + nn * 64 + 8 * dg);
            ulonglong2 b1 = *(const ulonglong2*)(Bs + nn * 64 + 8 * dg + 4);
            ffma2(acc[0][0], ap.x, b0.x); ffma2(acc[0][1], ap.x, b0.y);
            ffma2(acc[0][2], ap.x, b1.x); ffma2(acc[0][3], ap.x, b1.y);
            ffma2(acc[1][0], ap.y, b0.x); ffma2(acc[1][1], ap.y, b0.y);
            ffma2(acc[1][2], ap.y, b1.x); ffma2(acc[1][3], ap.y, b1.y);
        }
        __syncthreads();
    }
    float* out = g_S1 + ((size_t)(b * NXX + nx)) * KYY * DVV;
#pragma unroll
    for (int rp = 0; rp < 2; ++rp) {
        float2 q0 = unpack2(acc[rp][0]), q1 = unpack2(acc[rp][1]);
        float2 q2 = unpack2(acc[rp][2]), q3 = unpack2(acc[rp][3]);
        float* o = out + (4 * kg + 2 * rp) * 32 + 4 * dg;
        *(float4*)(o)      = make_float4(q0.x, q1.x, q2.x, q3.x);
        *(float4*)(o + 32) = make_float4(q0.y, q1.y, q2.y, q3.y);
    }
}

// ---------------------------------------------------------------------------
// Step 2: rFFT-X forward, truncated.
// S2r/i[b][kx][ky][dv] = sum_nx Ftr/Fti[nx][kx] * S1[b][nx][ky][dv]
// grid (KY, B), 128 threads. Packed pairs along kx; B duplicated.
// ---------------------------------------------------------------------------
__global__ __launch_bounds__(128) void k_step2() {
    __shared__ float Ar[32 * 64], Ai[32 * 64];
    __shared__ float Bs[32 * 64];   // duplicated dv
    int ky = blockIdx.x, b = blockIdx.y;
    int tid = threadIdx.x;
    int dg = tid & 7, kg = tid >> 3;
    const float* s1base = g_S1 + (size_t)b * NXX * KYY * DVV + (size_t)ky * DVV;

    u64 accr[2][4] = {}, acci[2][4] = {};
    for (int c = 0; c < 16; ++c) {
        const float4* sar = (const float4*)(g_Ftr + c * 32 * 64);
        const float4* sai = (const float4*)(g_Fti + c * 32 * 64);
#pragma unroll
        for (int t = 0; t < 4; ++t) {
            ((float4*)Ar)[tid + 128 * t] = sar[tid + 128 * t];
            ((float4*)Ai)[tid + 128 * t] = sai[tid + 128 * t];
        }
#pragma unroll
        for (int t = 0; t < 2; ++t) {
            int j = tid + 128 * t;
            int nn = j >> 3, q = j & 7;
            float4 v = *(const float4*)(s1base + (size_t)(c * 32 + nn) * KYY * DVV + 4 * q);
            float4* drow = (float4*)(Bs + nn * 64 + 8 * q);
            drow[0] = make_float4(v.x, v.x, v.y, v.y);
            drow[1] = make_float4(v.z, v.z, v.w, v.w);
        }
        __syncthreads();
#pragma unroll 8
        for (int nn = 0; nn < 32; ++nn) {
            ulonglong2 arp = *(const ulonglong2*)(Ar + nn * 64 + 4 * kg);
            ulonglong2 aip = *(const ulonglong2*)(Ai + nn * 64 + 4 * kg);
            ulonglong2 b0 = *(const ulonglong2*)(Bs + nn * 64 + 8 * dg);
            ulonglong2 b1 = *(const ulonglong2*)(Bs + nn * 64 + 8 * dg + 4);
            u64 bq[4] = {b0.x, b0.y, b1.x, b1.y};
#pragma unroll
            for (int q = 0; q < 4; ++q) {
                ffma2(accr[0][q], arp.x, bq[q]);
                ffma2(accr[1][q], arp.y, bq[q]);
                ffma2(acci[0][q], aip.x, bq[q]);
                ffma2(acci[1][q], aip.y, bq[q]);
            }
        }
        __syncthreads();
    }
#pragma unroll
    for (int rp = 0; rp < 2; ++rp) {
        float2 r0 = unpack2(accr[rp][0]), r1 = unpack2(accr[rp][1]);
        float2 r2 = unpack2(accr[rp][2]), r3 = unpack2(accr[rp][3]);
        float2 i0 = unpack2(acci[rp][0]), i1 = unpack2(acci[rp][1]);
        float2 i2 = unpack2(acci[rp][2]), i3 = unpack2(acci[rp][3]);
        int kx = 4 * kg + 2 * rp;
        size_t dst = (((size_t)b * KXX + kx) * KYY + ky) * DVV + 4 * dg;
        *(float4*)(g_S2r + dst)        = make_float4(r0.x, r1.x, r2.x, r3.x);
        *(float4*)(g_S2r + dst + 2048) = make_float4(r0.y, r1.y, r2.y, r3.y);
        *(float4*)(g_S2i + dst)        = make_float4(i0.x, i1.x, i2.x, i3.x);
        *(float4*)(g_S2i + dst + 2048) = make_float4(i0.y, i1.y, i2.y, i3.y);
    }
}

// ---------------------------------------------------------------------------
// Step 3: per-mode complex channel mix, ic split across blockIdx.z for occupancy.
// grid (KX, KY/16, 8), 256 threads. Output coalesced via smem transpose.
// ---------------------------------------------------------------------------
__global__ __launch_bounds__(256) void k_step3(const float* __restrict__ Rr,
                                               const float* __restrict__ Ri) {
    __shared__ float Xr[4 * 16 * 33], Xi[4 * 16 * 33];  // [e][u][j], pitch 33
    __shared__ float Sr[4 * 32 * 16], Si[4 * 32 * 16];  // [i4][j][u]
    __shared__ float Yr[64 * 4], Yi[64 * 4];            // [e*16+u][ii]
    int kx = blockIdx.x, ky0 = blockIdx.y * 16, ic = blockIdx.z;
    int tid = threadIdx.x;
    int lane = tid & 31, w = tid >> 5;

    // stage X (all e, 16 ky, 32 j)
#pragma unroll
    for (int r = 0; r < 8; ++r) {
        int row = w * 8 + r;
        int e = row >> 4, u = row & 15;
        size_t src = (((size_t)e * KXX + kx) * KYY + ky0 + u) * DVV + lane;
        Xr[(e * 16 + u) * 33 + lane] = g_S2r[src];
        Xi[(e * 16 + u) * 33 + lane] = g_S2i[src];
    }
    // stage R for this block's 4 output channels
#pragma unroll
    for (int t = 0; t < 8; ++t) {
        int flat = tid + 256 * t;
        int row = flat >> 4, uu = flat & 15;
        int i4 = row >> 5, j = row & 31;
        size_t src = (((size_t)(ic * 4 + i4) * DVV + j) * KXX + kx) * KYY + ky0 + uu;
        Sr[(i4 * 32 + j) * 16 + uu] = Rr[src];
        Si[(i4 * 32 + j) * 16 + uu] = Ri[src];
    }
    __syncthreads();

    int u = tid & 15, e = (tid >> 4) & 3, ii = tid >> 6;
    float ar = 0.f, ai = 0.f;
#pragma unroll 8
    for (int j = 0; j < 32; ++j) {
        float xr = Xr[(e * 16 + u) * 33 + j];
        float xi = Xi[(e * 16 + u) * 33 + j];
        float rr = Sr[(ii * 32 + j) * 16 + u];
        float ri = Si[(ii * 32 + j) * 16 + u];
        ar = fmaf(rr, xr, ar);
        ar = fmaf(-ri, xi, ar);
        ai = fmaf(rr, xi, ai);
        ai = fmaf(ri, xr, ai);
    }
    Yr[(e * 16 + u) * 4 + ii] = ar;
    Yi[(e * 16 + u) * 4 + ii] = ai;
    __syncthreads();

    if (tid < 128) {
        int row = tid & 63, which = tid >> 6;
        int ee = row >> 4, uu = row & 15;
        float4 v = ((const float4*)(which ? Yi : Yr))[row];
        size_t dst = (((size_t)ee * KYY + ky0 + uu) * KXX + kx) * DVV + ic * 4;
        *(float4*)((which ? g_S3i : g_S3r) + dst) = v;
    }
}

// ---------------------------------------------------------------------------
// Step 4: irFFT-X truncated.
// S4[b][nx][ky][dv] = sum_kx Gr[kx][nx]*S3r + Gi[kx][nx]*S3i
// grid (NX/128, KY, B), 128 threads. Packed pairs along nx; B duplicated.
// ---------------------------------------------------------------------------
__global__ __launch_bounds__(128) void k_step4() {
    __shared__ float Agr[32 * 128], Agi[32 * 128];
    __shared__ float Brd[32 * 64], Bid[32 * 64];
    int nx0 = blockIdx.x * 128, ky = blockIdx.y, b = blockIdx.z;
    int tid = threadIdx.x;
    int dg = tid & 7, ng = tid >> 3;

    u64 acc[4][4] = {};             // [nx-pair][dv]
    for (int c = 0; c < 2; ++c) {
#pragma unroll
        for (int t = 0; t < 8; ++t) {
            int flat = tid + 128 * t;
            int row = flat >> 5, q = flat & 31;
            ((float4*)Agr)[flat] = *(const float4*)(g_Gr + (c * 32 + row) * 512 + nx0 + 4 * q);
            ((float4*)Agi)[flat] = *(const float4*)(g_Gi + (c * 32 + row) * 512 + nx0 + 4 * q);
        }
        const float* sbr = g_S3r + (((size_t)b * KYY + ky) * KXX + c * 32) * DVV;
        const float* sbi = g_S3i + (((size_t)b * KYY + ky) * KXX + c * 32) * DVV;
#pragma unroll
        for (int t = 0; t < 2; ++t) {
            int j = tid + 128 * t;
            int nn = j >> 3, q = j & 7;
            float4 vr = ((const float4*)sbr)[j];
            float4 vi = ((const float4*)sbi)[j];
            float4* dr = (float4*)(Brd + nn * 64 + 8 * q);
            dr[0] = make_float4(vr.x, vr.x, vr.y, vr.y);
            dr[1] = make_float4(vr.z, vr.z, vr.w, vr.w);
            float4* di = (float4*)(Bid + nn * 64 + 8 * q);
            di[0] = make_float4(vi.x, vi.x, vi.y, vi.y);
            di[1] = make_float4(vi.z, vi.z, vi.w, vi.w);
        }
        __syncthreads();
#pragma unroll 4
        for (int kk = 0; kk < 32; ++kk) {
            ulonglong2 g0 = *(const ulonglong2*)(Agr + kk * 128 + 8 * ng);
            ulonglong2 g1 = *(const ulonglong2*)(Agr + kk * 128 + 8 * ng + 4);
            ulonglong2 h0 = *(const ulonglong2*)(Agi + kk * 128 + 8 * ng);
            ulonglong2 h1 = *(const ulonglong2*)(Agi + kk * 128 + 8 * ng + 4);
            ulonglong2 br0 = *(const ulonglong2*)(Brd + kk * 64 + 8 * dg);
            ulonglong2 br1 = *(const ulonglong2*)(Brd + kk * 64 + 8 * dg + 4);
            ulonglong2 bi0 = *(const ulonglong2*)(Bid + kk * 64 + 8 * dg);
            ulonglong2 bi1 = *(const ulonglong2*)(Bid + kk * 64 + 8 * dg + 4);
            u64 gp[4] = {g0.x, g0.y, g1.x, g1.y};
            u64 hp[4] = {h0.x, h0.y, h1.x, h1.y};
            u64 brq[4] = {br0.x, br0.y, br1.x, br1.y};
            u64 biq[4] = {bi0.x, bi0.y, bi1.x, bi1.y};
#pragma unroll
            for (int rp = 0; rp < 4; ++rp)
#pragma unroll
                for (int q = 0; q < 4; ++q) {
                    ffma2(acc[rp][q], gp[rp], brq[q]);
                    ffma2(acc[rp][q], hp[rp], biq[q]);
                }
        }
        __syncthreads();
    }
#pragma unroll
    for (int rp = 0; rp < 4; ++rp) {
        float2 q0 = unpack2(acc[rp][0]), q1 = unpack2(acc[rp][1]);
        float2 q2 = unpack2(acc[rp][2]), q3 = unpack2(acc[rp][3]);
        int nx = nx0 + 8 * ng + 2 * rp;
        size_t dst = (((size_t)(b * NXX + nx)) * KYY + ky) * DVV + 4 * dg;
        *(float4*)(g_S4 + dst)        = make_float4(q0.x, q1.x, q2.x, q3.x);
        *(float4*)(g_S4 + dst + 2048) = make_float4(q0.y, q1.y, q2.y, q3.y);
    }
}

// ---------------------------------------------------------------------------
// Step 5: iDCT-Y.  out[b][nx][ny][dv] = sum_ky Cr[ky][ny] * S4[b][nx][ky][dv]
// grid (NY/128, NX, B), 128 threads. Packed pairs along ny; B duplicated.
// ---------------------------------------------------------------------------
__global__ __launch_bounds__(128) void k_step5(float* __restrict__ out) {
    __shared__ float As[32 * 128];
    __shared__ float Bsd[32 * 64];
    int ny0 = blockIdx.x * 128, nx = blockIdx.y, b = blockIdx.z;
    int tid = threadIdx.x;
    int dg = tid & 7, ng = tid >> 3;

    u64 acc[4][4] = {};             // [ny-pair][dv]
    for (int c = 0; c < 2; ++c) {
#pragma unroll
        for (int t = 0; t < 8; ++t) {
            int flat = tid + 128 * t;
            int row = flat >> 5, q = flat & 31;
            ((float4*)As)[flat] = *(const float4*)(g_Cr + (c * 32 + row) * 512 + ny0 + 4 * q);
        }
        const float* sb = g_S4 + ((size_t)(b * NXX + nx) * KYY + c * 32) * DVV;
#pragma unroll
        for (int t = 0; t < 2; ++t) {
            int j = tid + 128 * t;
            int nn = j >> 3, q = j & 7;
            float4 v = ((const float4*)sb)[j];
            float4* drow = (float4*)(Bsd + nn * 64 + 8 * q);
            drow[0] = make_float4(v.x, v.x, v.y, v.y);
            drow[1] = make_float4(v.z, v.z, v.w, v.w);
        }
        __syncthreads();
#pragma unroll 4
        for (int kk = 0; kk < 32; ++kk) {
            ulonglong2 a0 = *(const ulonglong2*)(As + kk * 128 + 8 * ng);
            ulonglong2 a1 = *(const ulonglong2*)(As + kk * 128 + 8 * ng + 4);
            ulonglong2 b0 = *(const ulonglong2*)(Bsd + kk * 64 + 8 * dg);
            ulonglong2 b1 = *(const ulonglong2*)(Bsd + kk * 64 + 8 * dg + 4);
            u64 ap[4] = {a0.x, a0.y, a1.x, a1.y};
            u64 bq[4] = {b0.x, b0.y, b1.x, b1.y};
#pragma unroll
            for (int rp = 0; rp < 4; ++rp)
#pragma unroll
                for (int q = 0; q < 4; ++q)
                    ffma2(acc[rp][q], ap[rp], bq[q]);
        }
        __syncthreads();
    }
#pragma unroll
    for (int rp = 0; rp < 4; ++rp) {
        float2 q0 = unpack2(acc[rp][0]), q1 = unpack2(acc[rp][1]);
        float2 q2 = unpack2(acc[rp][2]), q3 = unpack2(acc[rp][3]);
        int ny = ny0 + 8 * ng + 2 * rp;
        size_t dst = ((size_t)(b * NXX + nx) * NYY + ny) * DVV + 4 * dg;
        *(float4*)(out + dst)      = make_float4(q0.x, q1.x, q2.x, q3.x);
        *(float4*)(out + dst + 32) = make_float4(q0.y, q1.y, q2.y, q3.y);
    }
}

// ---------------------------------------------------------------------------
extern "C" void kernel_launch(void* const* d_in, const int* in_sizes, int n_in,
                              void* d_out, int out_size) {
    const float* x  = (const float*)d_in[0];
    const float* Rr = (const float*)d_in[1];
    const float* Ri = (const float*)d_in[2];
    float* out = (float*)d_out;

    k_precompute<<<128, 256>>>();
    k_step1<<<dim3(NXX, BB), 128>>>(x);
    k_step2<<<dim3(KYY, BB), 128>>>();
    k_step3<<<dim3(KXX, KYY / 16, 8), 256>>>(Rr, Ri);
    k_step4<<<dim3(NXX / 128, KYY, BB), 128>>>();
    k_step5<<<dim3(NYY / 128, NXX, BB), 128>>>(out);
}

// round 4
// speedup vs baseline: 2.5918x; 2.5918x over previous
#include <cuda_runtime.h>
#include <cuda_bf16.h>
#include <math.h>
#include <stdint.h>

typedef unsigned long long u64;
typedef unsigned int u32;

#define BB  4
#define NXX 512
#define NYY 512
#define DVV 32
#define KXX 64
#define KYY 64
#define PI_D 3.14159265358979323846

#define SW128(o) ((o) ^ (((o) >> 3) & 0x70))

__device__ __forceinline__ u32 smem_u32(const void* p) {
    u32 a;
    asm("{ .reg .u64 t; cvta.to.shared.u64 t, %1; cvt.u32.u64 %0, t; }" : "=r"(a) : "l"(p));
    return a;
}
__device__ __forceinline__ void ldsm_x4(u32* r, u32 addr) {
    asm volatile("ldmatrix.sync.aligned.m8n8.x4.shared.b16 {%0,%1,%2,%3}, [%4];"
                 : "=r"(r[0]), "=r"(r[1]), "=r"(r[2]), "=r"(r[3]) : "r"(addr));
}
__device__ __forceinline__ void ldsm_x2(u32* r, u32 addr) {
    asm volatile("ldmatrix.sync.aligned.m8n8.x2.shared.b16 {%0,%1}, [%2];"
                 : "=r"(r[0]), "=r"(r[1]) : "r"(addr));
}
__device__ __forceinline__ void mma_bf16(float* d, const u32* a, const u32* b) {
    asm volatile("mma.sync.aligned.m16n8k16.row.col.f32.bf16.bf16.f32 "
                 "{%0,%1,%2,%3}, {%4,%5,%6,%7}, {%8,%9}, {%0,%1,%2,%3};"
                 : "+f"(d[0]), "+f"(d[1]), "+f"(d[2]), "+f"(d[3])
                 : "r"(a[0]), "r"(a[1]), "r"(a[2]), "r"(a[3]), "r"(b[0]), "r"(b[1]));
}
__device__ __forceinline__ void split_bf16(float v, __nv_bfloat16 &h, __nv_bfloat16 &l) {
    h = __float2bfloat16(v);
    l = __float2bfloat16(v - __bfloat162float(h));
}

// fp32 matrices for scalar steps 2/4
__device__ __align__(16) float g_Ftr[NXX*KXX];   // [n][k]
__device__ __align__(16) float g_Fti[NXX*KXX];
__device__ __align__(16) float g_Gr [KXX*NXX];   // [k][n]
__device__ __align__(16) float g_Gi [KXX*NXX];

// bf16 hi/lo B operands in *smem tile image* layout (ldmatrix-swizzled 128B rows)
// step1: 8 chunks of [64 rows ky][64 k=ny] (8KB each)
__device__ __align__(16) char g_B1h[KYY*NYY*2];
__device__ __align__(16) char g_B1l[KYY*NYY*2];
// step5: [512 rows ny][64 k=ky], used in 8 passes of 64 rows (8KB each)
__device__ __align__(16) char g_Bth[NYY*KYY*2];
__device__ __align__(16) char g_Btl[NYY*KYY*2];

// Scratch
__device__ __align__(16) float g_S1 [(size_t)BB*NXX*KYY*DVV];  // [b][nx][ky][dv]
__device__ __align__(16) float g_S2r[(size_t)BB*KXX*KYY*DVV];  // [b][kx][ky][dv]
__device__ __align__(16) float g_S2i[(size_t)BB*KXX*KYY*DVV];
__device__ __align__(16) float g_S3r[(size_t)BB*KYY*KXX*DVV];  // [b][ky][kx][dv]
__device__ __align__(16) float g_S3i[(size_t)BB*KYY*KXX*DVV];
__device__ __align__(16) float g_S4 [(size_t)BB*NXX*KYY*DVV];  // [b][nx][ky][dv]

// ---------------------------------------------------------------------------
// Precompute. DCT-II ortho C[k][n] = s_k cos(pi k (2n+1)/(2N)).
// ---------------------------------------------------------------------------
__global__ void k_precompute() {
    int idx = blockIdx.x * blockDim.x + threadIdx.x;
    if (idx >= KXX * NXX) return;
    int k = idx >> 9;          // 0..63
    int n = idx & 511;         // 0..511

    double sk = (k == 0) ? sqrt(1.0 / 512.0) : sqrt(2.0 / 512.0);
    int m = (k * (2 * n + 1)) & 2047;
    float Ckn = (float)(sk * cos(PI_D * (double)m / 1024.0));

    __nv_bfloat16 h, l;
    split_bf16(Ckn, h, l);
    // step1 B tile: chunk = n>>6, row = k (ky), col = n&63 (ny local)
    {
        u32 byte = (u32)(n >> 6) * 8192 + SW128((u32)(k * 128 + (n & 63) * 2));
        *(__nv_bfloat16*)(g_B1h + byte) = h;
        *(__nv_bfloat16*)(g_B1l + byte) = l;
    }
    // step5 B: row = n (ny), col = k (ky)
    {
        u32 byte = SW128((u32)(n * 128 + k * 2));
        *(__nv_bfloat16*)(g_Bth + byte) = h;
        *(__nv_bfloat16*)(g_Btl + byte) = l;
    }

    // rfft fp32 for scalar steps 2/4
    int mm = (k * n) & 511;
    double ang = 2.0 * PI_D * (double)mm / 512.0;
    double isq = sqrt(1.0 / 512.0);
    float fr = (float)( cos(ang) * isq);
    float fi = (float)(-sin(ang) * isq);
    g_Ftr[n * 64 + k] = fr;
    g_Fti[n * 64 + k] = fi;
    float ck = (k == 0) ? 1.0f : 2.0f;
    g_Gr[k * 512 + n] = ck * fr;
    g_Gi[k * 512 + n] = ck * fi;
}

// ---------------------------------------------------------------------------
// Step 1 (HMMA): per (b, nx-quad): D[m=(a,dv)=128][n=ky=64] = sum_ny A·B^T
// K=512 in 8 chunks of 64.  smem: AH@0 AL@16K BH@32K BL@40K  (48KB)
// ---------------------------------------------------------------------------
__global__ __launch_bounds__(128) void k_step1_mma(const float* __restrict__ x) {
    extern __shared__ char smem[];
    u32 sb = smem_u32(smem);
    const u32 sAH = sb, sAL = sb + 16384, sBH = sb + 32768, sBL = sb + 40960;
    int tid = threadIdx.x, w = tid >> 5, lane = tid & 31;
    int nx0 = blockIdx.x * 4, b = blockIdx.y;

    const float* xrow = x + ((size_t)(b * 512 + nx0 + w)) * 512 * 32 + lane;
    int mrow = w * 32 + lane;

    float acc[2][8][4] = {};

    for (int c = 0; c < 8; ++c) {
        // stage B chunk (linear copy of precomputed tile image)
        {
            const float4* sh = (const float4*)(g_B1h + c * 8192);
            const float4* sl = (const float4*)(g_B1l + c * 8192);
            float4* dh = (float4*)(smem + 32768);
            float4* dl = (float4*)(smem + 40960);
#pragma unroll
            for (int t = 0; t < 4; ++t) { dh[tid + 128 * t] = sh[tid + 128 * t]; dl[tid + 128 * t] = sl[tid + 128 * t]; }
        }
        // stage A chunk: transpose + hi/lo split
        {
            const float* xc = xrow + (size_t)c * 64 * 32;
#pragma unroll 8
            for (int j2 = 0; j2 < 32; ++j2) {
                float v0 = xc[(2 * j2) * 32];
                float v1 = xc[(2 * j2 + 1) * 32];
                __nv_bfloat16 h0, l0, h1, l1;
                split_bf16(v0, h0, l0);
                split_bf16(v1, h1, l1);
                u32 off = SW128((u32)(mrow * 128 + j2 * 4));
                *(__nv_bfloat162*)(smem + off) = __nv_bfloat162(h0, h1);
                *(__nv_bfloat162*)(smem + 16384 + off) = __nv_bfloat162(l0, l1);
            }
        }
        __syncthreads();

#pragma unroll
        for (int kk = 0; kk < 4; ++kk) {
            u32 ah[2][4], al[2][4], bh[8][2], bl[8][2];
#pragma unroll
            for (int mt = 0; mt < 2; ++mt) {
                u32 row = w * 32 + mt * 16 + (lane & 15);
                u32 blk = kk * 2 + (lane >> 4);
                u32 off = SW128(row * 128 + blk * 16);
                ldsm_x4(ah[mt], sAH + off);
                ldsm_x4(al[mt], sAL + off);
            }
#pragma unroll
            for (int nt = 0; nt < 8; ++nt) {
                u32 row = nt * 8 + (lane & 7);
                u32 blk = kk * 2 + ((lane >> 3) & 1);
                u32 off = SW128(row * 128 + blk * 16);
                ldsm_x2(bh[nt], sBH + off);
                ldsm_x2(bl[nt], sBL + off);
            }
#pragma unroll
            for (int mt = 0; mt < 2; ++mt)
#pragma unroll
                for (int nt = 0; nt < 8; ++nt) {
                    mma_bf16(acc[mt][nt], ah[mt], bh[nt]);
                    mma_bf16(acc[mt][nt], al[mt], bh[nt]);
                    mma_bf16(acc[mt][nt], ah[mt], bl[nt]);
                }
        }
        __syncthreads();
    }

    // epilogue: direct STG (lanes cover contiguous dv -> full 32B sectors)
    int g = lane >> 2, t4 = lane & 3;
    float* obase = g_S1 + ((size_t)(b * 512 + nx0 + w)) * 64 * 32;
#pragma unroll
    for (int mt = 0; mt < 2; ++mt)
#pragma unroll
        for (int nt = 0; nt < 8; ++nt) {
            int dv1 = mt * 16 + g, dv2 = dv1 + 8;
            int ky0 = nt * 8 + 2 * t4;
            obase[ky0 * 32 + dv1]       = acc[mt][nt][0];
            obase[(ky0 + 1) * 32 + dv1] = acc[mt][nt][1];
            obase[ky0 * 32 + dv2]       = acc[mt][nt][2];
            obase[(ky0 + 1) * 32 + dv2] = acc[mt][nt][3];
        }
}

// ---------------------------------------------------------------------------
// Step 2 (scalar, R1): S2 = rFFT-X of S1
// ---------------------------------------------------------------------------
__global__ __launch_bounds__(128) void k_step2() {
    __shared__ float Ar[32 * 64], Ai[32 * 64], Bs[32 * 32];
    int ky = blockIdx.x, b = blockIdx.y;
    int tid = threadIdx.x;
    int dg = tid & 7, kg = tid >> 3;
    const float* s1base = g_S1 + (size_t)b * NXX * KYY * DVV + (size_t)ky * DVV;

    float accr[4][4] = {}, acci[4][4] = {};
    for (int c = 0; c < 16; ++c) {
        const float4* sar = (const float4*)(g_Ftr + c * 32 * 64);
        const float4* sai = (const float4*)(g_Fti + c * 32 * 64);
#pragma unroll
        for (int t = 0; t < 4; ++t) {
            ((float4*)Ar)[tid + 128 * t] = sar[tid + 128 * t];
            ((float4*)Ai)[tid + 128 * t] = sai[tid + 128 * t];
        }
#pragma unroll
        for (int t = 0; t < 2; ++t) {
            int j = tid + 128 * t;
            int nn = j >> 3, q = j & 7;
            ((float4*)Bs)[j] = *(const float4*)(s1base + (size_t)(c * 32 + nn) * KYY * DVV + 4 * q);
        }
        __syncthreads();
#pragma unroll 8
        for (int nn = 0; nn < 32; ++nn) {
            float4 ar = *(const float4*)(Ar + nn * 64 + 4 * kg);
            float4 ai = *(const float4*)(Ai + nn * 64 + 4 * kg);
            float4 v  = *(const float4*)(Bs + nn * 32 + 4 * dg);
            float arr[4] = {ar.x, ar.y, ar.z, ar.w};
            float aii[4] = {ai.x, ai.y, ai.z, ai.w};
            float vv[4]  = {v.x, v.y, v.z, v.w};
#pragma unroll
            for (int r = 0; r < 4; ++r)
#pragma unroll
                for (int q = 0; q < 4; ++q) {
                    accr[r][q] = fmaf(arr[r], vv[q], accr[r][q]);
                    acci[r][q] = fmaf(aii[r], vv[q], acci[r][q]);
                }
        }
        __syncthreads();
    }
#pragma unroll
    for (int r = 0; r < 4; ++r) {
        int kx = 4 * kg + r;
        size_t dst = (((size_t)b * KXX + kx) * KYY + ky) * DVV + 4 * dg;
        *(float4*)(g_S2r + dst) = make_float4(accr[r][0], accr[r][1], accr[r][2], accr[r][3]);
        *(float4*)(g_S2i + dst) = make_float4(acci[r][0], acci[r][1], acci[r][2], acci[r][3]);
    }
}

// ---------------------------------------------------------------------------
// Step 3 (R2): per-mode complex channel mix, ic split on blockIdx.z
// ---------------------------------------------------------------------------
__global__ __launch_bounds__(256) void k_step3(const float* __restrict__ Rr,
                                               const float* __restrict__ Ri) {
    __shared__ float Xr[4 * 16 * 33], Xi[4 * 16 * 33];
    __shared__ float Sr[4 * 32 * 16], Si[4 * 32 * 16];
    __shared__ float Yr[64 * 4], Yi[64 * 4];
    int kx = blockIdx.x, ky0 = blockIdx.y * 16, ic = blockIdx.z;
    int tid = threadIdx.x;
    int lane = tid & 31, w = tid >> 5;

#pragma unroll
    for (int r = 0; r < 8; ++r) {
        int row = w * 8 + r;
        int e = row >> 4, u = row & 15;
        size_t src = (((size_t)e * KXX + kx) * KYY + ky0 + u) * DVV + lane;
        Xr[(e * 16 + u) * 33 + lane] = g_S2r[src];
        Xi[(e * 16 + u) * 33 + lane] = g_S2i[src];
    }
#pragma unroll
    for (int t = 0; t < 8; ++t) {
        int flat = tid + 256 * t;
        int row = flat >> 4, uu = flat & 15;
        int i4 = row >> 5, j = row & 31;
        size_t src = (((size_t)(ic * 4 + i4) * DVV + j) * KXX + kx) * KYY + ky0 + uu;
        Sr[(i4 * 32 + j) * 16 + uu] = Rr[src];
        Si[(i4 * 32 + j) * 16 + uu] = Ri[src];
    }
    __syncthreads();

    int u = tid & 15, e = (tid >> 4) & 3, ii = tid >> 6;
    float ar = 0.f, ai = 0.f;
#pragma unroll 8
    for (int j = 0; j < 32; ++j) {
        float xr = Xr[(e * 16 + u) * 33 + j];
        float xi = Xi[(e * 16 + u) * 33 + j];
        float rr = Sr[(ii * 32 + j) * 16 + u];
        float ri = Si[(ii * 32 + j) * 16 + u];
        ar = fmaf(rr, xr, ar);
        ar = fmaf(-ri, xi, ar);
        ai = fmaf(rr, xi, ai);
        ai = fmaf(ri, xr, ai);
    }
    Yr[(e * 16 + u) * 4 + ii] = ar;
    Yi[(e * 16 + u) * 4 + ii] = ai;
    __syncthreads();

    if (tid < 128) {
        int row = tid & 63, which = tid >> 6;
        int ee = row >> 4, uu = row & 15;
        float4 v = ((const float4*)(which ? Yi : Yr))[row];
        size_t dst = (((size_t)ee * KYY + ky0 + uu) * KXX + kx) * DVV + ic * 4;
        *(float4*)((which ? g_S3i : g_S3r) + dst) = v;
    }
}

// ---------------------------------------------------------------------------
// Step 4 (scalar, R1): irFFT-X truncated
// ---------------------------------------------------------------------------
__global__ __launch_bounds__(128) void k_step4() {
    __shared__ float Agr[32 * 128], Agi[32 * 128], Br[32 * 32], Bi[32 * 32];
    int nx0 = blockIdx.x * 128, ky = blockIdx.y, b = blockIdx.z;
    int tid = threadIdx.x;
    int dg = tid & 7, ng = tid >> 3;

    float acc[8][4] = {};
    for (int c = 0; c < 2; ++c) {
#pragma unroll
        for (int t = 0; t < 8; ++t) {
            int flat = tid + 128 * t;
            int row = flat >> 5, q = flat & 31;
            ((float4*)Agr)[flat] = *(const float4*)(g_Gr + (c * 32 + row) * 512 + nx0 + 4 * q);
            ((float4*)Agi)[flat] = *(const float4*)(g_Gi + (c * 32 + row) * 512 + nx0 + 4 * q);
        }
        const float4* sbr = (const float4*)(g_S3r + (((size_t)b * KYY + ky) * KXX + c * 32) * DVV);
        const float4* sbi = (const float4*)(g_S3i + (((size_t)b * KYY + ky) * KXX + c * 32) * DVV);
#pragma unroll
        for (int t = 0; t < 2; ++t) {
            ((float4*)Br)[tid + 128 * t] = sbr[tid + 128 * t];
            ((float4*)Bi)[tid + 128 * t] = sbi[tid + 128 * t];
        }
        __syncthreads();
#pragma unroll 4
        for (int kk = 0; kk < 32; ++kk) {
            float4 g0 = *(const float4*)(Agr + kk * 128 + 8 * ng);
            float4 g1 = *(const float4*)(Agr + kk * 128 + 8 * ng + 4);
            float4 h0 = *(const float4*)(Agi + kk * 128 + 8 * ng);
            float4 h1 = *(const float4*)(Agi + kk * 128 + 8 * ng + 4);
            float4 br = *(const float4*)(Br + kk * 32 + 4 * dg);
            float4 bi = *(const float4*)(Bi + kk * 32 + 4 * dg);
            float gg[8] = {g0.x, g0.y, g0.z, g0.w, g1.x, g1.y, g1.z, g1.w};
            float hh[8] = {h0.x, h0.y, h0.z, h0.w, h1.x, h1.y, h1.z, h1.w};
            float brr[4] = {br.x, br.y, br.z, br.w};
            float bii[4] = {bi.x, bi.y, bi.z, bi.w};
#pragma unroll
            for (int r = 0; r < 8; ++r)
#pragma unroll
                for (int q = 0; q < 4; ++q) {
                    acc[r][q] = fmaf(gg[r], brr[q], acc[r][q]);
                    acc[r][q] = fmaf(hh[r], bii[q], acc[r][q]);
                }
        }
        __syncthreads();
    }
#pragma unroll
    for (int r = 0; r < 8; ++r) {
        size_t dst = (((size_t)(b * NXX + nx0 + 8 * ng + r)) * KYY + ky) * DVV + 4 * dg;
        *(float4*)(g_S4 + dst) = make_float4(acc[r][0], acc[r][1], acc[r][2], acc[r][3]);
    }
}

// ---------------------------------------------------------------------------
// Step 5 (HMMA): per (b, nx-quad): D[m=(a,dv)=128][n=ny], K=ky=64.
// N=512 in 8 passes of 64. A frags preloaded; B streamed per pass.
// smem: AH@0 AL@16K BH@32K BL@40K  (48KB)
// ---------------------------------------------------------------------------
__global__ __launch_bounds__(128) void k_step5_mma(float* __restrict__ out) {
    extern __shared__ char smem[];
    u32 sb = smem_u32(smem);
    const u32 sAH = sb, sAL = sb + 16384, sBH = sb + 32768, sBL = sb + 40960;
    int tid = threadIdx.x, w = tid >> 5, lane = tid & 31;
    int nx0 = blockIdx.x * 4, b = blockIdx.y;

    // stage A (K=64) once
    {
        int mrow = w * 32 + lane;
        const float* s4row = g_S4 + ((size_t)(b * 512 + nx0 + w)) * 64 * 32 + lane;
#pragma unroll 8
        for (int k2 = 0; k2 < 32; ++k2) {
            float v0 = s4row[(2 * k2) * 32];
            float v1 = s4row[(2 * k2 + 1) * 32];
            __nv_bfloat16 h0, l0, h1, l1;
            split_bf16(v0, h0, l0);
            split_bf16(v1, h1, l1);
            u32 off = SW128((u32)(mrow * 128 + k2 * 4));
            *(__nv_bfloat162*)(smem + off) = __nv_bfloat162(h0, h1);
            *(__nv_bfloat162*)(smem + 16384 + off) = __nv_bfloat162(l0, l1);
        }
    }
    __syncthreads();

    // preload all A fragments
    u32 ah[2][4][4], al[2][4][4];
#pragma unroll
    for (int mt = 0; mt < 2; ++mt)
#pragma unroll
        for (int kk = 0; kk < 4; ++kk) {
            u32 row = w * 32 + mt * 16 + (lane & 15);
            u32 blk = kk * 2 + (lane >> 4);
            u32 off = SW128(row * 128 + blk * 16);
            ldsm_x4(ah[mt][kk], sAH + off);
            ldsm_x4(al[mt][kk], sAL + off);
        }

    int g = lane >> 2, t4 = lane & 3;
    float* obase = out + ((size_t)(b * 512 + nx0 + w)) * 512 * 32;

    for (int p = 0; p < 8; ++p) {
        __syncthreads();
        // stage B pass tile (linear copy)
        {
            const float4* sh = (const float4*)(g_Bth + p * 8192);
            const float4* sl = (const float4*)(g_Btl + p * 8192);
            float4* dh = (float4*)(smem + 32768);
            float4* dl = (float4*)(smem + 40960);
#pragma unroll
            for (int t = 0; t < 4; ++t) { dh[tid + 128 * t] = sh[tid + 128 * t]; dl[tid + 128 * t] = sl[tid + 128 * t]; }
        }
        __syncthreads();

#pragma unroll
        for (int nt = 0; nt < 8; ++nt) {
            u32 bh[4][2], bl[4][2];
#pragma unroll
            for (int kk = 0; kk < 4; ++kk) {
                u32 row = nt * 8 + (lane & 7);
                u32 blk = kk * 2 + ((lane >> 3) & 1);
                u32 off = SW128(row * 128 + blk * 16);
                ldsm_x2(bh[kk], sBH + off);
                ldsm_x2(bl[kk], sBL + off);
            }
            float acc[2][4] = {};
#pragma unroll
            for (int kk = 0; kk < 4; ++kk)
#pragma unroll
                for (int mt = 0; mt < 2; ++mt) {
                    mma_bf16(acc[mt], ah[mt][kk], bh[kk]);
                    mma_bf16(acc[mt], al[mt][kk], bh[kk]);
                    mma_bf16(acc[mt], ah[mt][kk], bl[kk]);
                }
#pragma unroll
            for (int mt = 0; mt < 2; ++mt) {
                int dv1 = mt * 16 + g, dv2 = dv1 + 8;
                int ny0 = p * 64 + nt * 8 + 2 * t4;
                obase[(size_t)ny0 * 32 + dv1]       = acc[mt][0];
                obase[(size_t)(ny0 + 1) * 32 + dv1] = acc[mt][1];
                obase[(size_t)ny0 * 32 + dv2]       = acc[mt][2];
                obase[(size_t)(ny0 + 1) * 32 + dv2] = acc[mt][3];
            }
        }
    }
}

// ---------------------------------------------------------------------------
extern "C" void kernel_launch(void* const* d_in, const int* in_sizes, int n_in,
                              void* d_out, int out_size) {
    const float* x  = (const float*)d_in[0];
    const float* Rr = (const float*)d_in[1];
    const float* Ri = (const float*)d_in[2];
    float* out = (float*)d_out;

    k_precompute<<<128, 256>>>();
    k_step1_mma<<<dim3(128, BB), 128, 49152>>>(x);
    k_step2<<<dim3(KYY, BB), 128>>>();
    k_step3<<<dim3(KXX, KYY / 16, 8), 256>>>(Rr, Ri);
    k_step4<<<dim3(NXX / 128, KYY, BB), 128>>>();
    k_step5_mma<<<dim3(128, BB), 128, 49152>>>(out);
}